// round 5
// baseline (speedup 1.0000x reference)
#include <cuda_runtime.h>

#define Bsz 64
#define Tsz 128
#define INsz 257
#define Hsz 1024
#define Gsz 4096
#define MROWS (Bsz*Tsz)   /* 8192 */

// ---------------- scratch (static device memory; no allocations) ----------
__device__ float g_xg[MROWS * Gsz];   // input-projection gates, [B*T, 4H]
__device__ float g_y [MROWS * Hsz];   // layer outputs h per step, [B, T, H]
__device__ float g_c [Bsz * Hsz];     // running cell state

typedef unsigned long long ull;

__device__ __forceinline__ ull pk(float x, float y) {
    ull r; asm("mov.b64 %0,{%1,%2};" : "=l"(r) : "f"(x), "f"(y)); return r;
}
__device__ __forceinline__ ull f2(ull a, ull b, ull c) {
    ull d; asm("fma.rn.f32x2 %0,%1,%2,%3;" : "=l"(d) : "l"(a), "l"(b), "l"(c)); return d;
}
__device__ __forceinline__ float2 upk(ull v) {
    float lo, hi; asm("mov.b64 {%0,%1},%2;" : "=f"(lo), "=f"(hi) : "l"(v));
    return make_float2(lo, hi);
}
__device__ __forceinline__ ull ld2s(const float* p) {
    return *reinterpret_cast<const ull*>(p);
}
__device__ __forceinline__ float sigm(float x) { return 1.f / (1.f + __expf(-x)); }
__device__ __forceinline__ float tanh_acc(float x) {
    float e = __expf(-2.f * fabsf(x));
    float r = (1.f - e) / (1.f + e);
    return copysignf(r, x);
}

// ---------------- GEMM: g_xg[M,4096] = A[M,K] @ W[4096,K]^T + b0 + b1 -----
#define GBK 16
__global__ __launch_bounds__(256, 1)
void gemm_bias(const float* __restrict__ Ain, int a_is_y,
               const float* __restrict__ W,
               const float* __restrict__ b0v, const float* __restrict__ b1v,
               int K)
{
    const float* A = a_is_y ? g_y : Ain;
    __shared__ float As[GBK][132];
    __shared__ float Ws[GBK][132];
    const int n0 = blockIdx.x * 128, m0 = blockIdx.y * 128;
    const int tid = threadIdx.x;
    const int tn = (tid & 15) << 3, tm = (tid >> 4) << 3;

    ull acc[8][4];
#pragma unroll
    for (int i = 0; i < 8; i++)
#pragma unroll
        for (int j = 0; j < 4; j++) acc[i][j] = 0ull;

    for (int kk = 0; kk < K; kk += GBK) {
#pragma unroll
        for (int i = 0; i < 8; i++) {
            int idx = tid + (i << 8);
            int k = idx & 15, m = idx >> 4;
            int gk = kk + k;
            float av = 0.f, wv = 0.f;
            if (gk < K) {
                av = A[(m0 + m) * K + gk];
                wv = W[(n0 + m) * K + gk];
            }
            As[k][m] = av;
            Ws[k][m] = wv;
        }
        __syncthreads();
#pragma unroll
        for (int k = 0; k < GBK; k++) {
            ull wv0 = ld2s(&Ws[k][tn]);
            ull wv1 = ld2s(&Ws[k][tn + 2]);
            ull wv2 = ld2s(&Ws[k][tn + 4]);
            ull wv3 = ld2s(&Ws[k][tn + 6]);
#pragma unroll
            for (int ih = 0; ih < 4; ih++) {
                float2 a2 = *reinterpret_cast<const float2*>(&As[k][tm + 2 * ih]);
                ull ap0 = pk(a2.x, a2.x);
                ull ap1 = pk(a2.y, a2.y);
                int i0 = 2 * ih;
                acc[i0][0] = f2(ap0, wv0, acc[i0][0]);
                acc[i0][1] = f2(ap0, wv1, acc[i0][1]);
                acc[i0][2] = f2(ap0, wv2, acc[i0][2]);
                acc[i0][3] = f2(ap0, wv3, acc[i0][3]);
                acc[i0+1][0] = f2(ap1, wv0, acc[i0+1][0]);
                acc[i0+1][1] = f2(ap1, wv1, acc[i0+1][1]);
                acc[i0+1][2] = f2(ap1, wv2, acc[i0+1][2]);
                acc[i0+1][3] = f2(ap1, wv3, acc[i0+1][3]);
            }
        }
        __syncthreads();
    }

    float bias[8];
#pragma unroll
    for (int j = 0; j < 8; j++) bias[j] = b0v[n0 + tn + j] + b1v[n0 + tn + j];
#pragma unroll
    for (int i = 0; i < 8; i++) {
        float* crow = &g_xg[(m0 + tm + i) * Gsz + n0 + tn];
#pragma unroll
        for (int j = 0; j < 4; j++) {
            float2 v = upk(acc[i][j]);
            v.x += bias[2 * j];
            v.y += bias[2 * j + 1];
            *reinterpret_cast<float2*>(&crow[2 * j]) = v;
        }
    }
}

// ---------------- one LSTM timestep -----------------------------------
// Block owns 8 hidden columns (j0..j0+7) x all 4 gates x all 64 batches.
// gates = xg[:,t,:] + h_prev @ Whh^T ; fused cell update; h -> g_y[:,t,:]
__global__ __launch_bounds__(256, 1)
void lstm_step(const float* __restrict__ Whh,
               const float* __restrict__ h0l,
               const float* __restrict__ c0l,
               int t)
{
    __shared__ float hs[32][66];   // [k][b]
    __shared__ float ws[32][34];   // [k][r]  r = q*8 + jj
    __shared__ float gbuf[32][68]; // accumulated gates [r][b]
    __shared__ float xs[64][33];   // staged xg [b][r]

    const int j0 = blockIdx.x << 3;
    const int tid = threadIdx.x;

    const float* hp; int hstride;
    if (t == 0) { hp = h0l;                 hstride = Hsz; }
    else        { hp = g_y + (t - 1) * Hsz; hstride = Tsz * Hsz; }
    const float* csrc = (t == 0) ? c0l : g_c;

    const int r0 = (tid & 15) << 1;   // 2 gate-rows per thread
    const int m0 = (tid >> 4) << 2;   // 4 batches per thread
    ull acc[2][2] = {{0ull, 0ull}, {0ull, 0ull}};

    for (int kk = 0; kk < Hsz; kk += 32) {
#pragma unroll
        for (int i = 0; i < 8; i++) {
            int idx = tid + (i << 8);
            int k = idx & 31, b = idx >> 5;
            hs[k][b] = hp[b * hstride + kk + k];
        }
#pragma unroll
        for (int i = 0; i < 4; i++) {
            int idx = tid + (i << 8);
            int k = idx & 31, r = idx >> 5;
            int wrow = ((r >> 3) << 10) + j0 + (r & 7);
            ws[k][r] = Whh[wrow * Hsz + kk + k];
        }
        __syncthreads();
#pragma unroll
        for (int k = 0; k < 32; k++) {
            float2 w2 = *reinterpret_cast<const float2*>(&ws[k][r0]);
            ull wp0 = pk(w2.x, w2.x);
            ull wp1 = pk(w2.y, w2.y);
            ull hv0 = ld2s(&hs[k][m0]);
            ull hv1 = ld2s(&hs[k][m0 + 2]);
            acc[0][0] = f2(wp0, hv0, acc[0][0]);
            acc[0][1] = f2(wp0, hv1, acc[0][1]);
            acc[1][0] = f2(wp1, hv0, acc[1][0]);
            acc[1][1] = f2(wp1, hv1, acc[1][1]);
        }
        __syncthreads();
    }

#pragma unroll
    for (int rr = 0; rr < 2; rr++)
#pragma unroll
        for (int j = 0; j < 2; j++) {
            float2 v = upk(acc[rr][j]);
            gbuf[r0 + rr][m0 + 2 * j]     = v.x;
            gbuf[r0 + rr][m0 + 2 * j + 1] = v.y;
        }

#pragma unroll
    for (int i = 0; i < 8; i++) {
        int ii = tid + (i << 8);
        int b = ii >> 5, rem = ii & 31;
        int q = rem >> 3, jj = rem & 7;
        xs[b][rem] = g_xg[((b << 7) + t) * Gsz + (q << 10) + j0 + jj];
    }
    __syncthreads();

#pragma unroll
    for (int half = 0; half < 2; half++) {
        int cell = tid + (half << 8);
        int jj = cell >> 6, b = cell & 63;
        float iv = gbuf[jj][b]      + xs[b][jj];
        float fv = gbuf[8 + jj][b]  + xs[b][8 + jj];
        float gv = gbuf[16 + jj][b] + xs[b][16 + jj];
        float ov = gbuf[24 + jj][b] + xs[b][24 + jj];
        float co = csrc[b * Hsz + j0 + jj];
        float cn = sigm(fv) * co + sigm(iv) * tanh_acc(gv);
        g_c[b * Hsz + j0 + jj] = cn;
        g_y[((b << 7) + t) * Hsz + j0 + jj] = sigm(ov) * tanh_acc(cn);
    }
}

// ---------------- final projection: out = tanh(y2) @ Wy^T + by ----------
__global__ void out_proj(const float* __restrict__ Wy,
                         const float* __restrict__ by,
                         float* __restrict__ out)
{
    const int m = blockIdx.x;
    const float* y = g_y + (long)m * Hsz;
    float s0 = 0.f, s1 = 0.f;
    for (int k = threadIdx.x; k < Hsz; k += 128) {
        float th = tanh_acc(y[k]);
        s0 += th * Wy[k];
        s1 += th * Wy[Hsz + k];
    }
#pragma unroll
    for (int o = 16; o; o >>= 1) {
        s0 += __shfl_down_sync(0xffffffffu, s0, o);
        s1 += __shfl_down_sync(0xffffffffu, s1, o);
    }
    __shared__ float red[2][4];
    int w = threadIdx.x >> 5;
    if ((threadIdx.x & 31) == 0) { red[0][w] = s0; red[1][w] = s1; }
    __syncthreads();
    if (threadIdx.x == 0) {
        out[m * 2 + 0] = red[0][0] + red[0][1] + red[0][2] + red[0][3] + by[0];
        out[m * 2 + 1] = red[1][0] + red[1][1] + red[1][2] + red[1][3] + by[1];
    }
}

// ---------------- launch ------------------------------------------------
extern "C" void kernel_launch(void* const* d_in, const int* in_sizes, int n_in,
                              void* d_out, int out_size)
{
    const float* X    = (const float*)d_in[0];
    const float* h0   = (const float*)d_in[1];
    const float* c0   = (const float*)d_in[2];
    const float* Wih0 = (const float*)d_in[3];
    const float* Whh0 = (const float*)d_in[4];
    const float* bih0 = (const float*)d_in[5];
    const float* bhh0 = (const float*)d_in[6];
    const float* Wih1 = (const float*)d_in[7];
    const float* Whh1 = (const float*)d_in[8];
    const float* bih1 = (const float*)d_in[9];
    const float* bhh1 = (const float*)d_in[10];
    const float* Wy   = (const float*)d_in[11];
    const float* by   = (const float*)d_in[12];
    float* out = (float*)d_out;

    dim3 ggrid(Gsz / 128, MROWS / 128);  // (32, 64)

    // layer 0
    gemm_bias<<<ggrid, 256>>>(X, 0, Wih0, bih0, bhh0, INsz);
    for (int t = 0; t < Tsz; t++)
        lstm_step<<<128, 256>>>(Whh0, h0, c0, t);

    // layer 1
    gemm_bias<<<ggrid, 256>>>(nullptr, 1, Wih1, bih1, bhh1, Hsz);
    for (int t = 0; t < Tsz; t++)
        lstm_step<<<128, 256>>>(Whh1, h0 + Bsz * Hsz, c0 + Bsz * Hsz, t);

    // output projection
    out_proj<<<MROWS, 128>>>(Wy, by, out);
}

// round 6
// speedup vs baseline: 1.0442x; 1.0442x over previous
#include <cuda_runtime.h>

#define Bsz 64
#define Tsz 128
#define INsz 257
#define Hsz 1024
#define Gsz 4096
#define MROWS (Bsz*Tsz)   /* 8192 */

// ---------------- scratch (static device memory; no allocations) ----------
__device__ float g_xg[MROWS * Gsz];   // input-projection gates, [B*T, 4H]
__device__ float g_y [MROWS * Hsz];   // layer outputs h per step, [B, T, H]
__device__ float g_c [Bsz * Hsz];     // running cell state

typedef unsigned long long ull;

__device__ __forceinline__ ull pk(float x, float y) {
    ull r; asm("mov.b64 %0,{%1,%2};" : "=l"(r) : "f"(x), "f"(y)); return r;
}
__device__ __forceinline__ ull f2(ull a, ull b, ull c) {
    ull d; asm("fma.rn.f32x2 %0,%1,%2,%3;" : "=l"(d) : "l"(a), "l"(b), "l"(c)); return d;
}
__device__ __forceinline__ float2 upk(ull v) {
    float lo, hi; asm("mov.b64 {%0,%1},%2;" : "=f"(lo), "=f"(hi) : "l"(v));
    return make_float2(lo, hi);
}
__device__ __forceinline__ ull ld2s(const float* p) {
    return *reinterpret_cast<const ull*>(p);
}
__device__ __forceinline__ float sigm(float x) { return 1.f / (1.f + __expf(-x)); }
__device__ __forceinline__ float tanh_acc(float x) {
    float e = __expf(-2.f * fabsf(x));
    float r = (1.f - e) / (1.f + e);
    return copysignf(r, x);
}

// ---------------- GEMM: g_xg[M,4096] = A[M,K] @ W[4096,K]^T + b0 + b1 -----
#define GBK 16
__global__ __launch_bounds__(256, 1)
void gemm_bias(const float* __restrict__ Ain, int a_is_y,
               const float* __restrict__ W,
               const float* __restrict__ b0v, const float* __restrict__ b1v,
               int K)
{
    const float* A = a_is_y ? g_y : Ain;
    __shared__ float As[GBK][132];
    __shared__ float Ws[GBK][132];
    const int n0 = blockIdx.x * 128, m0 = blockIdx.y * 128;
    const int tid = threadIdx.x;
    const int tn = (tid & 15) << 3, tm = (tid >> 4) << 3;

    ull acc[8][4];
#pragma unroll
    for (int i = 0; i < 8; i++)
#pragma unroll
        for (int j = 0; j < 4; j++) acc[i][j] = 0ull;

    for (int kk = 0; kk < K; kk += GBK) {
#pragma unroll
        for (int i = 0; i < 8; i++) {
            int idx = tid + (i << 8);
            int k = idx & 15, m = idx >> 4;
            int gk = kk + k;
            float av = 0.f, wv = 0.f;
            if (gk < K) {
                av = A[(m0 + m) * K + gk];
                wv = W[(n0 + m) * K + gk];
            }
            As[k][m] = av;
            Ws[k][m] = wv;
        }
        __syncthreads();
#pragma unroll
        for (int k = 0; k < GBK; k++) {
            ull wv0 = ld2s(&Ws[k][tn]);
            ull wv1 = ld2s(&Ws[k][tn + 2]);
            ull wv2 = ld2s(&Ws[k][tn + 4]);
            ull wv3 = ld2s(&Ws[k][tn + 6]);
#pragma unroll
            for (int ih = 0; ih < 4; ih++) {
                float2 a2 = *reinterpret_cast<const float2*>(&As[k][tm + 2 * ih]);
                ull ap0 = pk(a2.x, a2.x);
                ull ap1 = pk(a2.y, a2.y);
                int i0 = 2 * ih;
                acc[i0][0] = f2(ap0, wv0, acc[i0][0]);
                acc[i0][1] = f2(ap0, wv1, acc[i0][1]);
                acc[i0][2] = f2(ap0, wv2, acc[i0][2]);
                acc[i0][3] = f2(ap0, wv3, acc[i0][3]);
                acc[i0+1][0] = f2(ap1, wv0, acc[i0+1][0]);
                acc[i0+1][1] = f2(ap1, wv1, acc[i0+1][1]);
                acc[i0+1][2] = f2(ap1, wv2, acc[i0+1][2]);
                acc[i0+1][3] = f2(ap1, wv3, acc[i0+1][3]);
            }
        }
        __syncthreads();
    }

    float bias[8];
#pragma unroll
    for (int j = 0; j < 8; j++) bias[j] = b0v[n0 + tn + j] + b1v[n0 + tn + j];
#pragma unroll
    for (int i = 0; i < 8; i++) {
        float* crow = &g_xg[(m0 + tm + i) * Gsz + n0 + tn];
#pragma unroll
        for (int j = 0; j < 4; j++) {
            float2 v = upk(acc[i][j]);
            v.x += bias[2 * j];
            v.y += bias[2 * j + 1];
            *reinterpret_cast<float2*>(&crow[2 * j]) = v;
        }
    }
}

// ---------------- one LSTM timestep -----------------------------------
// Block owns 8 hidden columns (j0..j0+7) x all 4 gates x all 64 batches.
// gates = xg[:,t,:] + h_prev @ Whh^T ; fused cell update; h -> g_y[:,t,:]
__global__ __launch_bounds__(256, 1)
void lstm_step(const float* __restrict__ Whh,
               const float* __restrict__ h0l,
               const float* __restrict__ c0l,
               int t)
{
    __shared__ float hs[32][66];   // [k][b]
    __shared__ float ws[32][34];   // [k][r]  r = q*8 + jj
    __shared__ float gbuf[32][68]; // accumulated gates [r][b]
    __shared__ float xs[64][33];   // staged xg [b][r]

    const int j0 = blockIdx.x << 3;
    const int tid = threadIdx.x;

    const float* hp; int hstride;
    if (t == 0) { hp = h0l;                 hstride = Hsz; }
    else        { hp = g_y + (t - 1) * Hsz; hstride = Tsz * Hsz; }
    const float* csrc = (t == 0) ? c0l : g_c;

    const int r0 = (tid & 15) << 1;   // 2 gate-rows per thread
    const int m0 = (tid >> 4) << 2;   // 4 batches per thread
    ull acc[2][2] = {{0ull, 0ull}, {0ull, 0ull}};

    for (int kk = 0; kk < Hsz; kk += 32) {
#pragma unroll
        for (int i = 0; i < 8; i++) {
            int idx = tid + (i << 8);
            int k = idx & 31, b = idx >> 5;
            hs[k][b] = hp[b * hstride + kk + k];
        }
#pragma unroll
        for (int i = 0; i < 4; i++) {
            int idx = tid + (i << 8);
            int k = idx & 31, r = idx >> 5;
            int wrow = ((r >> 3) << 10) + j0 + (r & 7);
            ws[k][r] = Whh[wrow * Hsz + kk + k];
        }
        __syncthreads();
#pragma unroll
        for (int k = 0; k < 32; k++) {
            float2 w2 = *reinterpret_cast<const float2*>(&ws[k][r0]);
            ull wp0 = pk(w2.x, w2.x);
            ull wp1 = pk(w2.y, w2.y);
            ull hv0 = ld2s(&hs[k][m0]);
            ull hv1 = ld2s(&hs[k][m0 + 2]);
            acc[0][0] = f2(wp0, hv0, acc[0][0]);
            acc[0][1] = f2(wp0, hv1, acc[0][1]);
            acc[1][0] = f2(wp1, hv0, acc[1][0]);
            acc[1][1] = f2(wp1, hv1, acc[1][1]);
        }
        __syncthreads();
    }

#pragma unroll
    for (int rr = 0; rr < 2; rr++)
#pragma unroll
        for (int j = 0; j < 2; j++) {
            float2 v = upk(acc[rr][j]);
            gbuf[r0 + rr][m0 + 2 * j]     = v.x;
            gbuf[r0 + rr][m0 + 2 * j + 1] = v.y;
        }

#pragma unroll
    for (int i = 0; i < 8; i++) {
        int ii = tid + (i << 8);
        int b = ii >> 5, rem = ii & 31;
        int q = rem >> 3, jj = rem & 7;
        xs[b][rem] = g_xg[((b << 7) + t) * Gsz + (q << 10) + j0 + jj];
    }
    __syncthreads();

#pragma unroll
    for (int half = 0; half < 2; half++) {
        int cell = tid + (half << 8);
        int jj = cell >> 6, b = cell & 63;
        float iv = gbuf[jj][b]      + xs[b][jj];
        float fv = gbuf[8 + jj][b]  + xs[b][8 + jj];
        float gv = gbuf[16 + jj][b] + xs[b][16 + jj];
        float ov = gbuf[24 + jj][b] + xs[b][24 + jj];
        float co = csrc[b * Hsz + j0 + jj];
        float cn = sigm(fv) * co + sigm(iv) * tanh_acc(gv);
        g_c[b * Hsz + j0 + jj] = cn;
        g_y[((b << 7) + t) * Hsz + j0 + jj] = sigm(ov) * tanh_acc(cn);
    }
}

// ---------------- final projection: out = tanh(y2) @ Wy^T + by ----------
__global__ void out_proj(const float* __restrict__ Wy,
                         const float* __restrict__ by,
                         float* __restrict__ out)
{
    const int m = blockIdx.x;
    const float* y = g_y + (long)m * Hsz;
    float s0 = 0.f, s1 = 0.f;
    for (int k = threadIdx.x; k < Hsz; k += 128) {
        float th = tanh_acc(y[k]);
        s0 += th * Wy[k];
        s1 += th * Wy[Hsz + k];
    }
#pragma unroll
    for (int o = 16; o; o >>= 1) {
        s0 += __shfl_down_sync(0xffffffffu, s0, o);
        s1 += __shfl_down_sync(0xffffffffu, s1, o);
    }
    __shared__ float red[2][4];
    int w = threadIdx.x >> 5;
    if ((threadIdx.x & 31) == 0) { red[0][w] = s0; red[1][w] = s1; }
    __syncthreads();
    if (threadIdx.x == 0) {
        out[m * 2 + 0] = red[0][0] + red[0][1] + red[0][2] + red[0][3] + by[0];
        out[m * 2 + 1] = red[1][0] + red[1][1] + red[1][2] + red[1][3] + by[1];
    }
}

// ---------------- launch ------------------------------------------------
extern "C" void kernel_launch(void* const* d_in, const int* in_sizes, int n_in,
                              void* d_out, int out_size)
{
    const float* X    = (const float*)d_in[0];
    const float* h0   = (const float*)d_in[1];
    const float* c0   = (const float*)d_in[2];
    const float* Wih0 = (const float*)d_in[3];
    const float* Whh0 = (const float*)d_in[4];
    const float* bih0 = (const float*)d_in[5];
    const float* bhh0 = (const float*)d_in[6];
    const float* Wih1 = (const float*)d_in[7];
    const float* Whh1 = (const float*)d_in[8];
    const float* bih1 = (const float*)d_in[9];
    const float* bhh1 = (const float*)d_in[10];
    const float* Wy   = (const float*)d_in[11];
    const float* by   = (const float*)d_in[12];
    float* out = (float*)d_out;

    dim3 ggrid(Gsz / 128, MROWS / 128);  // (32, 64)

    // layer 0
    gemm_bias<<<ggrid, 256>>>(X, 0, Wih0, bih0, bhh0, INsz);
    for (int t = 0; t < Tsz; t++)
        lstm_step<<<128, 256>>>(Whh0, h0, c0, t);

    // layer 1
    gemm_bias<<<ggrid, 256>>>(nullptr, 1, Wih1, bih1, bhh1, Hsz);
    for (int t = 0; t < Tsz; t++)
        lstm_step<<<128, 256>>>(Whh1, h0 + Bsz * Hsz, c0 + Bsz * Hsz, t);

    // output projection
    out_proj<<<MROWS, 128>>>(Wy, by, out);
}